// round 3
// baseline (speedup 1.0000x reference)
#include <cuda_runtime.h>
#include <math.h>

// Problem constants (fixed shapes from reference setup_inputs)
#define BSZ   2
#define SEQ   1024
#define DM    1024
#define DI    2048
#define NS    16
#define DTR   64
#define ROWS  (BSZ*SEQ)     // 2048
#define CHUNK_T 256
#define NC    (SEQ/CHUNK_T) // 4
#define XPW   96            // dt_rank + 2*n_state

// ---------------- scratch (device globals; no allocation allowed) ----------
__device__ float g_xr[ROWS * 2 * DI];   // in_proj output: [xc | res], 2048 x 4096
__device__ float g_u[ROWS * DI];        // conv+silu output
__device__ float g_xp[ROWS * XPW];      // x_proj output (dlt | B | C)
__device__ float g_delta[ROWS * DI];    // softplus(dt_proj)
__device__ float g_g[ROWS * DI];        // y * silu(res)

// ---------------- generic tiled SGEMM: C[M,N] = A[M,K] @ W[N,K]^T + bias ----
// BM=BN=128, BK=16, 256 threads, 8x8 per thread. All dims divide tiles evenly.
// EPI: 0 = bias only, 1 = bias + softplus
template<int EPI>
__global__ __launch_bounds__(256)
void gemm128(const float* __restrict__ A, int lda,
             const float* __restrict__ W, int ldw,
             const float* __restrict__ bias,
             float* __restrict__ C, int N, int K)
{
    __shared__ float As[16][132];
    __shared__ float Ws[16][132];

    const int tid = threadIdx.x;
    const int tx = tid & 15;          // col group
    const int ty = tid >> 4;          // row group
    const int m0 = blockIdx.y * 128;
    const int n0 = blockIdx.x * 128;

    float acc[8][8];
    #pragma unroll
    for (int i = 0; i < 8; i++)
        #pragma unroll
        for (int j = 0; j < 8; j++) acc[i][j] = 0.f;

    for (int k0 = 0; k0 < K; k0 += 16) {
        // load 128x16 A-tile and 128x16 W-tile (512 float4 each; 2/thread)
        #pragma unroll
        for (int i = 0; i < 2; i++) {
            int f   = tid + i * 256;
            int row = f >> 2;
            int kq  = (f & 3) << 2;
            float4 va = *(const float4*)(A + (size_t)(m0 + row) * lda + k0 + kq);
            As[kq + 0][row] = va.x; As[kq + 1][row] = va.y;
            As[kq + 2][row] = va.z; As[kq + 3][row] = va.w;
            float4 vw = *(const float4*)(W + (size_t)(n0 + row) * ldw + k0 + kq);
            Ws[kq + 0][row] = vw.x; Ws[kq + 1][row] = vw.y;
            Ws[kq + 2][row] = vw.z; Ws[kq + 3][row] = vw.w;
        }
        __syncthreads();

        #pragma unroll
        for (int k = 0; k < 16; k++) {
            float a[8], b[8];
            *(float4*)(a)     = *(const float4*)&As[k][ty * 8];
            *(float4*)(a + 4) = *(const float4*)&As[k][ty * 8 + 4];
            *(float4*)(b)     = *(const float4*)&Ws[k][tx * 8];
            *(float4*)(b + 4) = *(const float4*)&Ws[k][tx * 8 + 4];
            #pragma unroll
            for (int i = 0; i < 8; i++)
                #pragma unroll
                for (int j = 0; j < 8; j++)
                    acc[i][j] = fmaf(a[i], b[j], acc[i][j]);
        }
        __syncthreads();
    }

    // epilogue
    #pragma unroll
    for (int i = 0; i < 8; i++) {
        int m = m0 + ty * 8 + i;
        #pragma unroll
        for (int j = 0; j < 8; j++) {
            int n = n0 + tx * 8 + j;
            float v = acc[i][j] + bias[n];
            if (EPI == 1) {
                // numerically stable softplus
                v = fmaxf(v, 0.f) + log1pf(expf(-fabsf(v)));
            }
            C[(size_t)m * N + n] = v;
        }
    }
}

// ---------------- skinny GEMM: xp[2048,96] = u[2048,2048] @ W_x[96,2048]^T ---
// BM=16, BN=96, KT=32, 128 threads; thread computes 4 rows x 3 cols.
__global__ __launch_bounds__(128)
void gemm_skinny(const float* __restrict__ A,
                 const float* __restrict__ W,
                 float* __restrict__ C)
{
    __shared__ float As[32][17];
    __shared__ float Ws[32][97];

    const int tid = threadIdx.x;
    const int tx = tid & 31;   // cols tx*3 .. tx*3+2
    const int ty = tid >> 5;   // rows ty*4 .. ty*4+3
    const int m0 = blockIdx.x * 16;

    float acc[4][3];
    #pragma unroll
    for (int i = 0; i < 4; i++)
        #pragma unroll
        for (int j = 0; j < 3; j++) acc[i][j] = 0.f;

    for (int k0 = 0; k0 < DI; k0 += 32) {
        {   // A tile: 16x32 = 128 float4, 1/thread
            int row = tid >> 3;
            int kq  = (tid & 7) << 2;
            float4 v = *(const float4*)(A + (size_t)(m0 + row) * DI + k0 + kq);
            As[kq + 0][row] = v.x; As[kq + 1][row] = v.y;
            As[kq + 2][row] = v.z; As[kq + 3][row] = v.w;
        }
        #pragma unroll
        for (int i = 0; i < 6; i++) {  // W tile: 96x32 = 768 float4, 6/thread
            int f   = tid + i * 128;
            int row = f >> 3;
            int kq  = (f & 7) << 2;
            float4 v = *(const float4*)(W + (size_t)row * DI + k0 + kq);
            Ws[kq + 0][row] = v.x; Ws[kq + 1][row] = v.y;
            Ws[kq + 2][row] = v.z; Ws[kq + 3][row] = v.w;
        }
        __syncthreads();

        #pragma unroll
        for (int k = 0; k < 32; k++) {
            float a0 = As[k][ty * 4 + 0], a1 = As[k][ty * 4 + 1];
            float a2 = As[k][ty * 4 + 2], a3 = As[k][ty * 4 + 3];
            float b0 = Ws[k][tx * 3 + 0], b1 = Ws[k][tx * 3 + 1], b2 = Ws[k][tx * 3 + 2];
            acc[0][0] = fmaf(a0, b0, acc[0][0]); acc[0][1] = fmaf(a0, b1, acc[0][1]); acc[0][2] = fmaf(a0, b2, acc[0][2]);
            acc[1][0] = fmaf(a1, b0, acc[1][0]); acc[1][1] = fmaf(a1, b1, acc[1][1]); acc[1][2] = fmaf(a1, b2, acc[1][2]);
            acc[2][0] = fmaf(a2, b0, acc[2][0]); acc[2][1] = fmaf(a2, b1, acc[2][1]); acc[2][2] = fmaf(a2, b2, acc[2][2]);
            acc[3][0] = fmaf(a3, b0, acc[3][0]); acc[3][1] = fmaf(a3, b1, acc[3][1]); acc[3][2] = fmaf(a3, b2, acc[3][2]);
        }
        __syncthreads();
    }

    #pragma unroll
    for (int i = 0; i < 4; i++)
        #pragma unroll
        for (int j = 0; j < 3; j++)
            C[(size_t)(m0 + ty * 4 + i) * XPW + tx * 3 + j] = acc[i][j];
}

// ---------------- causal depthwise conv (k=3) + SiLU ------------------------
__global__ __launch_bounds__(256)
void conv_silu(const float* __restrict__ xr,
               const float* __restrict__ cw,
               const float* __restrict__ cb,
               float* __restrict__ u)
{
    int idx = blockIdx.x * blockDim.x + threadIdx.x;   // 0 .. ROWS*DI-1
    int d   = idx & (DI - 1);
    int row = idx >> 11;
    int l   = row & (SEQ - 1);
    const float* base = xr + (size_t)row * (2 * DI) + d;  // xc branch (first half)
    float w0 = cw[d * 3 + 0], w1 = cw[d * 3 + 1], w2 = cw[d * 3 + 2];
    float acc = fmaf(w2, base[0], cb[d]);
    if (l >= 1) acc = fmaf(w1, base[-(2 * DI)], acc);
    if (l >= 2) acc = fmaf(w0, base[-(4 * DI)], acc);
    u[idx] = acc / (1.f + __expf(-acc));   // silu
}

// ---------------- chunked selective scan + output gating --------------------
// grid (BSZ*NC, DI/128), block 128. One thread per (b, chunk, d) lane.
__global__ __launch_bounds__(128)
void scan_kernel(const float* __restrict__ A_log,
                 const float* __restrict__ delta,
                 const float* __restrict__ u,
                 const float* __restrict__ xr,
                 const float* __restrict__ xp,
                 float* __restrict__ gout)
{
    const int bc = blockIdx.x;                 // b*NC + c
    const int b  = bc / NC;
    const int c  = bc - b * NC;
    const int d  = blockIdx.y * 128 + threadIdx.x;
    const int row0 = b * SEQ + c * CHUNK_T;

    float Aa[NS], st[NS];
    #pragma unroll
    for (int n = 0; n < NS; n++) {
        Aa[n] = -expf(A_log[d * NS + n]);
        st[n] = 0.f;
    }

    __shared__ float Bs[16][NS];
    __shared__ float Cs[16][NS];

    for (int t0 = 0; t0 < CHUNK_T; t0 += 16) {
        __syncthreads();
        // 16 timesteps x (16 B + 16 C) = 512 values; 4 per thread
        #pragma unroll
        for (int i = 0; i < 4; i++) {
            int e   = threadIdx.x + i * 128;
            int tl  = e >> 5;
            int rem = e & 31;
            float v = xp[(size_t)(row0 + t0 + tl) * XPW + DTR + rem];
            if (rem < NS) Bs[tl][rem]       = v;
            else          Cs[tl][rem - NS]  = v;
        }
        __syncthreads();

        #pragma unroll 4
        for (int tt = 0; tt < 16; tt++) {
            const int row = row0 + t0 + tt;
            float dv = delta[(size_t)row * DI + d];
            float uv = u[(size_t)row * DI + d];
            float rv = xr[(size_t)row * (2 * DI) + DI + d];   // res branch
            float du = dv * uv;
            float y  = 0.f;
            #pragma unroll
            for (int n = 0; n < NS; n++) {
                float a = __expf(dv * Aa[n]);
                st[n] = fmaf(a, st[n], du * Bs[tt][n]);
                y     = fmaf(st[n], Cs[tt][n], y);
            }
            float gate = rv / (1.f + __expf(-rv));
            gout[(size_t)row * DI + d] = y * gate;
        }
    }
}

// ---------------- launch ----------------------------------------------------
extern "C" void kernel_launch(void* const* d_in, const int* in_sizes, int n_in,
                              void* d_out, int out_size)
{
    const float* x      = (const float*)d_in[0];
    const float* W_in   = (const float*)d_in[1];
    const float* b_in   = (const float*)d_in[2];
    const float* conv_w = (const float*)d_in[3];
    const float* conv_b = (const float*)d_in[4];
    const float* W_x    = (const float*)d_in[5];
    const float* W_dt   = (const float*)d_in[6];
    const float* b_dt   = (const float*)d_in[7];
    const float* A_log  = (const float*)d_in[8];
    const float* W_out  = (const float*)d_in[9];
    const float* b_out  = (const float*)d_in[10];
    float* out = (float*)d_out;

    float *xr, *u, *xp, *delta, *g;
    cudaGetSymbolAddress((void**)&xr,    g_xr);
    cudaGetSymbolAddress((void**)&u,     g_u);
    cudaGetSymbolAddress((void**)&xp,    g_xp);
    cudaGetSymbolAddress((void**)&delta, g_delta);
    cudaGetSymbolAddress((void**)&g,     g_g);

    // 1) in_proj: xr[2048,4096] = x @ W_in^T + b_in
    gemm128<0><<<dim3(2 * DI / 128, ROWS / 128), 256>>>(x, DM, W_in, DM, b_in, xr, 2 * DI, DM);

    // 2) depthwise causal conv + silu -> u
    conv_silu<<<(ROWS * DI) / 256, 256>>>(xr, conv_w, conv_b, u);

    // 3) x_proj: xp[2048,96] = u @ W_x^T
    gemm_skinny<<<ROWS / 16, 128>>>(u, W_x, xp);

    // 4) dt_proj + softplus: delta[2048,2048] = softplus(xp[:, :64] @ W_dt^T + b_dt)
    gemm128<1><<<dim3(DI / 128, ROWS / 128), 256>>>(xp, XPW, W_dt, DTR, b_dt, delta, DI, DTR);

    // 5) chunked selective scan + gating -> g = y * silu(res)
    scan_kernel<<<dim3(BSZ * NC, DI / 128), 128>>>(A_log, delta, u, xr, xp, g);

    // 6) out_proj: out[2048,1024] = g @ W_out^T + b_out
    gemm128<0><<<dim3(DM / 128, ROWS / 128), 256>>>(g, DI, W_out, DI, b_out, out, DM, DI);
}

// round 4
// speedup vs baseline: 1.4134x; 1.4134x over previous
#include <cuda_runtime.h>
#include <cuda_bf16.h>
#include <mma.h>
#include <math.h>

using namespace nvcuda;

// Problem constants (fixed shapes from reference setup_inputs)
#define BSZ   2
#define SEQ   1024
#define DM    1024
#define DI    2048
#define NS    16
#define DTR   64
#define ROWS  (BSZ*SEQ)     // 2048
#define CHUNK_T 256
#define NC    (SEQ/CHUNK_T) // 4
#define XPW   96            // dt_rank + 2*n_state

// ---------------- scratch (device globals; no allocation allowed) ----------
__device__ float g_xr[ROWS * 2 * DI];   // in_proj output (RAW, bias folded later)
__device__ float g_u[ROWS * DI];        // conv+silu output
__device__ float g_xp[ROWS * XPW];      // x_proj output (dlt | B | C)
__device__ float g_delta[ROWS * DI];    // softplus(dt_proj)
__device__ float g_g[ROWS * DI];        // y * silu(res)

// bf16 hi/lo split buffers
__device__ __nv_bfloat16 g_xh[ROWS * DM],  g_xl[ROWS * DM];      // x split
__device__ __nv_bfloat16 g_wih[2*DI * DM], g_wil[2*DI * DM];     // W_in split
__device__ __nv_bfloat16 g_gh[ROWS * DI],  g_gl[ROWS * DI];      // g split
__device__ __nv_bfloat16 g_woh[DM * DI],   g_wol[DM * DI];       // W_out split

// ---------------- bf16 hi/lo split ------------------------------------------
__global__ __launch_bounds__(256)
void split_bf16(const float* __restrict__ src,
                __nv_bfloat16* __restrict__ hi,
                __nv_bfloat16* __restrict__ lo, int n)
{
    int i = blockIdx.x * blockDim.x + threadIdx.x;
    if (i < n) {
        float v = src[i];
        __nv_bfloat16 h = __float2bfloat16(v);
        float r = v - __bfloat162float(h);
        hi[i] = h;
        lo[i] = __float2bfloat16(r);
    }
}

// ---------------- bf16x3 tensor-core GEMM -----------------------------------
// C[M,N] (raw, no bias) = A[M,K] @ W[N,K]^T with A,W given as bf16 hi/lo pairs.
// Block tile 128x128, BK=32, 512 threads (16 warps, 4x4), warp tile 32x32.
#define BKP 40   // padded smem ld (multiple of 8)
__global__ __launch_bounds__(512)
void gemm_bf16x3(const __nv_bfloat16* __restrict__ Ah,
                 const __nv_bfloat16* __restrict__ Al,
                 const __nv_bfloat16* __restrict__ Bh,
                 const __nv_bfloat16* __restrict__ Bl,
                 float* __restrict__ C, int N, int K)
{
    __shared__ __align__(16) __nv_bfloat16 As_h[128 * BKP];
    __shared__ __align__(16) __nv_bfloat16 As_l[128 * BKP];
    __shared__ __align__(16) __nv_bfloat16 Bs_h[128 * BKP];
    __shared__ __align__(16) __nv_bfloat16 Bs_l[128 * BKP];

    const int tid = threadIdx.x;
    const int wid = tid >> 5;
    const int wr  = wid >> 2;          // warp row 0..3
    const int wc  = wid & 3;           // warp col 0..3
    const int m0  = blockIdx.y * 128;
    const int n0  = blockIdx.x * 128;

    wmma::fragment<wmma::accumulator, 16, 16, 16, float> acc[2][2];
    #pragma unroll
    for (int i = 0; i < 2; i++)
        #pragma unroll
        for (int j = 0; j < 2; j++) wmma::fill_fragment(acc[i][j], 0.0f);

    const int lrow = tid >> 2;              // 0..127
    const int lkq  = (tid & 3) * 8;         // 0,8,16,24

    for (int k0 = 0; k0 < K; k0 += 32) {
        // each thread: one 8-bf16 (16B) chunk per tile
        {
            size_t ga = (size_t)(m0 + lrow) * K + k0 + lkq;
            size_t gb = (size_t)(n0 + lrow) * K + k0 + lkq;
            int so = lrow * BKP + lkq;
            *(float4*)&As_h[so] = *(const float4*)(Ah + ga);
            *(float4*)&As_l[so] = *(const float4*)(Al + ga);
            *(float4*)&Bs_h[so] = *(const float4*)(Bh + gb);
            *(float4*)&Bs_l[so] = *(const float4*)(Bl + gb);
        }
        __syncthreads();

        #pragma unroll
        for (int kk = 0; kk < 32; kk += 16) {
            wmma::fragment<wmma::matrix_a, 16, 16, 16, __nv_bfloat16, wmma::row_major> ah[2], al[2];
            wmma::fragment<wmma::matrix_b, 16, 16, 16, __nv_bfloat16, wmma::col_major> bh[2], bl[2];
            #pragma unroll
            for (int i = 0; i < 2; i++) {
                int r = (wr * 32 + i * 16) * BKP + kk;
                wmma::load_matrix_sync(ah[i], &As_h[r], BKP);
                wmma::load_matrix_sync(al[i], &As_l[r], BKP);
            }
            #pragma unroll
            for (int j = 0; j < 2; j++) {
                int r = (wc * 32 + j * 16) * BKP + kk;
                wmma::load_matrix_sync(bh[j], &Bs_h[r], BKP);
                wmma::load_matrix_sync(bl[j], &Bs_l[r], BKP);
            }
            #pragma unroll
            for (int i = 0; i < 2; i++)
                #pragma unroll
                for (int j = 0; j < 2; j++) {
                    wmma::mma_sync(acc[i][j], ah[i], bh[j], acc[i][j]);
                    wmma::mma_sync(acc[i][j], ah[i], bl[j], acc[i][j]);
                    wmma::mma_sync(acc[i][j], al[i], bh[j], acc[i][j]);
                }
        }
        __syncthreads();
    }

    #pragma unroll
    for (int i = 0; i < 2; i++)
        #pragma unroll
        for (int j = 0; j < 2; j++) {
            float* p = C + (size_t)(m0 + wr * 32 + i * 16) * N + n0 + wc * 32 + j * 16;
            wmma::store_matrix_sync(p, acc[i][j], N, wmma::mem_row_major);
        }
}

// ---------------- fp32 tiled SGEMM (kept for dt_proj) -----------------------
template<int EPI>
__global__ __launch_bounds__(256)
void gemm128(const float* __restrict__ A, int lda,
             const float* __restrict__ W, int ldw,
             const float* __restrict__ bias,
             float* __restrict__ C, int N, int K)
{
    __shared__ float As[16][132];
    __shared__ float Ws[16][132];

    const int tid = threadIdx.x;
    const int tx = tid & 15;
    const int ty = tid >> 4;
    const int m0 = blockIdx.y * 128;
    const int n0 = blockIdx.x * 128;

    float acc[8][8];
    #pragma unroll
    for (int i = 0; i < 8; i++)
        #pragma unroll
        for (int j = 0; j < 8; j++) acc[i][j] = 0.f;

    for (int k0 = 0; k0 < K; k0 += 16) {
        #pragma unroll
        for (int i = 0; i < 2; i++) {
            int f   = tid + i * 256;
            int row = f >> 2;
            int kq  = (f & 3) << 2;
            float4 va = *(const float4*)(A + (size_t)(m0 + row) * lda + k0 + kq);
            As[kq + 0][row] = va.x; As[kq + 1][row] = va.y;
            As[kq + 2][row] = va.z; As[kq + 3][row] = va.w;
            float4 vw = *(const float4*)(W + (size_t)(n0 + row) * ldw + k0 + kq);
            Ws[kq + 0][row] = vw.x; Ws[kq + 1][row] = vw.y;
            Ws[kq + 2][row] = vw.z; Ws[kq + 3][row] = vw.w;
        }
        __syncthreads();

        #pragma unroll
        for (int k = 0; k < 16; k++) {
            float a[8], b[8];
            *(float4*)(a)     = *(const float4*)&As[k][ty * 8];
            *(float4*)(a + 4) = *(const float4*)&As[k][ty * 8 + 4];
            *(float4*)(b)     = *(const float4*)&Ws[k][tx * 8];
            *(float4*)(b + 4) = *(const float4*)&Ws[k][tx * 8 + 4];
            #pragma unroll
            for (int i = 0; i < 8; i++)
                #pragma unroll
                for (int j = 0; j < 8; j++)
                    acc[i][j] = fmaf(a[i], b[j], acc[i][j]);
        }
        __syncthreads();
    }

    #pragma unroll
    for (int i = 0; i < 8; i++) {
        int m = m0 + ty * 8 + i;
        #pragma unroll
        for (int j = 0; j < 8; j++) {
            int n = n0 + tx * 8 + j;
            float v = acc[i][j] + bias[n];
            if (EPI == 1) v = fmaxf(v, 0.f) + log1pf(expf(-fabsf(v)));
            C[(size_t)m * N + n] = v;
        }
    }
}

// ---------------- skinny GEMM: xp[2048,96] = u @ W_x^T, 256 threads ----------
__global__ __launch_bounds__(256)
void gemm_skinny(const float* __restrict__ A,
                 const float* __restrict__ W,
                 float* __restrict__ C)
{
    __shared__ float As[32][17];
    __shared__ float Ws[32][97];

    const int tid = threadIdx.x;
    const int tx = tid & 31;   // cols tx*3 .. tx*3+2
    const int ty = tid >> 5;   // rows ty*2 .. ty*2+1
    const int m0 = blockIdx.x * 16;

    float acc[2][3];
    #pragma unroll
    for (int i = 0; i < 2; i++)
        #pragma unroll
        for (int j = 0; j < 3; j++) acc[i][j] = 0.f;

    for (int k0 = 0; k0 < DI; k0 += 32) {
        if (tid < 128) {   // A tile: 16x32 = 128 float4
            int row = tid >> 3;
            int kq  = (tid & 7) << 2;
            float4 v = *(const float4*)(A + (size_t)(m0 + row) * DI + k0 + kq);
            As[kq + 0][row] = v.x; As[kq + 1][row] = v.y;
            As[kq + 2][row] = v.z; As[kq + 3][row] = v.w;
        }
        #pragma unroll
        for (int i = 0; i < 3; i++) {  // W tile: 96x32 = 768 float4
            int f   = tid + i * 256;
            int row = f >> 3;
            int kq  = (f & 7) << 2;
            float4 v = *(const float4*)(W + (size_t)row * DI + k0 + kq);
            Ws[kq + 0][row] = v.x; Ws[kq + 1][row] = v.y;
            Ws[kq + 2][row] = v.z; Ws[kq + 3][row] = v.w;
        }
        __syncthreads();

        #pragma unroll
        for (int k = 0; k < 32; k++) {
            float a0 = As[k][ty * 2 + 0], a1 = As[k][ty * 2 + 1];
            float b0 = Ws[k][tx * 3 + 0], b1 = Ws[k][tx * 3 + 1], b2 = Ws[k][tx * 3 + 2];
            acc[0][0] = fmaf(a0, b0, acc[0][0]); acc[0][1] = fmaf(a0, b1, acc[0][1]); acc[0][2] = fmaf(a0, b2, acc[0][2]);
            acc[1][0] = fmaf(a1, b0, acc[1][0]); acc[1][1] = fmaf(a1, b1, acc[1][1]); acc[1][2] = fmaf(a1, b2, acc[1][2]);
        }
        __syncthreads();
    }

    #pragma unroll
    for (int i = 0; i < 2; i++)
        #pragma unroll
        for (int j = 0; j < 3; j++)
            C[(size_t)(m0 + ty * 2 + i) * XPW + tx * 3 + j] = acc[i][j];
}

// ---------------- causal depthwise conv (k=3) + SiLU (b_in folded in) --------
__global__ __launch_bounds__(256)
void conv_silu(const float* __restrict__ xr,
               const float* __restrict__ b_in,
               const float* __restrict__ cw,
               const float* __restrict__ cb,
               float* __restrict__ u)
{
    int idx = blockIdx.x * blockDim.x + threadIdx.x;   // 0 .. ROWS*DI-1
    int d   = idx & (DI - 1);
    int row = idx >> 11;
    int l   = row & (SEQ - 1);
    const float* base = xr + (size_t)row * (2 * DI) + d;  // xc branch (first half)
    float bin = b_in[d];
    float w0 = cw[d * 3 + 0], w1 = cw[d * 3 + 1], w2 = cw[d * 3 + 2];
    float acc = fmaf(w2, base[0] + bin, cb[d]);
    if (l >= 1) acc = fmaf(w1, base[-(2 * DI)] + bin, acc);
    if (l >= 2) acc = fmaf(w0, base[-(4 * DI)] + bin, acc);
    u[idx] = acc / (1.f + __expf(-acc));   // silu
}

// ---------------- chunked selective scan + output gating --------------------
__global__ __launch_bounds__(128)
void scan_kernel(const float* __restrict__ A_log,
                 const float* __restrict__ delta,
                 const float* __restrict__ u,
                 const float* __restrict__ xr,
                 const float* __restrict__ b_in,
                 const float* __restrict__ xp,
                 float* __restrict__ gout)
{
    const int bc = blockIdx.x;                 // b*NC + c
    const int b  = bc / NC;
    const int c  = bc - b * NC;
    const int d  = blockIdx.y * 128 + threadIdx.x;
    const int row0 = b * SEQ + c * CHUNK_T;
    const float bres = b_in[DI + d];

    float Aa[NS], st[NS];
    #pragma unroll
    for (int n = 0; n < NS; n++) {
        Aa[n] = -expf(A_log[d * NS + n]);
        st[n] = 0.f;
    }

    __shared__ float Bs[16][NS];
    __shared__ float Cs[16][NS];

    for (int t0 = 0; t0 < CHUNK_T; t0 += 16) {
        __syncthreads();
        #pragma unroll
        for (int i = 0; i < 4; i++) {
            int e   = threadIdx.x + i * 128;
            int tl  = e >> 5;
            int rem = e & 31;
            float v = xp[(size_t)(row0 + t0 + tl) * XPW + DTR + rem];
            if (rem < NS) Bs[tl][rem]       = v;
            else          Cs[tl][rem - NS]  = v;
        }
        __syncthreads();

        #pragma unroll 4
        for (int tt = 0; tt < 16; tt++) {
            const int row = row0 + t0 + tt;
            float dv = delta[(size_t)row * DI + d];
            float uv = u[(size_t)row * DI + d];
            float rv = xr[(size_t)row * (2 * DI) + DI + d] + bres;  // res + b_in
            float du = dv * uv;
            float y  = 0.f;
            #pragma unroll
            for (int n = 0; n < NS; n++) {
                float a = __expf(dv * Aa[n]);
                st[n] = fmaf(a, st[n], du * Bs[tt][n]);
                y     = fmaf(st[n], Cs[tt][n], y);
            }
            float gate = rv / (1.f + __expf(-rv));
            gout[(size_t)row * DI + d] = y * gate;
        }
    }
}

// ---------------- final bias add --------------------------------------------
__global__ __launch_bounds__(256)
void add_bias(float* __restrict__ C, const float* __restrict__ b, int n)
{
    int i = blockIdx.x * blockDim.x + threadIdx.x;
    if (i < n) C[i] += b[i & (DM - 1)];
}

// ---------------- launch ----------------------------------------------------
extern "C" void kernel_launch(void* const* d_in, const int* in_sizes, int n_in,
                              void* d_out, int out_size)
{
    const float* x      = (const float*)d_in[0];
    const float* W_in   = (const float*)d_in[1];
    const float* b_in   = (const float*)d_in[2];
    const float* conv_w = (const float*)d_in[3];
    const float* conv_b = (const float*)d_in[4];
    const float* W_x    = (const float*)d_in[5];
    const float* W_dt   = (const float*)d_in[6];
    const float* b_dt   = (const float*)d_in[7];
    const float* A_log  = (const float*)d_in[8];
    const float* W_out  = (const float*)d_in[9];
    const float* b_out  = (const float*)d_in[10];
    float* out = (float*)d_out;

    float *xr, *u, *xp, *delta, *g;
    cudaGetSymbolAddress((void**)&xr,    g_xr);
    cudaGetSymbolAddress((void**)&u,     g_u);
    cudaGetSymbolAddress((void**)&xp,    g_xp);
    cudaGetSymbolAddress((void**)&delta, g_delta);
    cudaGetSymbolAddress((void**)&g,     g_g);

    __nv_bfloat16 *xh, *xl, *wih, *wil, *gh, *gl, *woh, *wol;
    cudaGetSymbolAddress((void**)&xh,  g_xh);
    cudaGetSymbolAddress((void**)&xl,  g_xl);
    cudaGetSymbolAddress((void**)&wih, g_wih);
    cudaGetSymbolAddress((void**)&wil, g_wil);
    cudaGetSymbolAddress((void**)&gh,  g_gh);
    cudaGetSymbolAddress((void**)&gl,  g_gl);
    cudaGetSymbolAddress((void**)&woh, g_woh);
    cudaGetSymbolAddress((void**)&wol, g_wol);

    // 0) bf16 hi/lo splits for GEMM1 operands
    split_bf16<<<(ROWS * DM + 255) / 256, 256>>>(x, xh, xl, ROWS * DM);
    split_bf16<<<(2 * DI * DM + 255) / 256, 256>>>(W_in, wih, wil, 2 * DI * DM);

    // 1) in_proj (tensor core, bf16x3): xr_raw[2048,4096] = x @ W_in^T
    gemm_bf16x3<<<dim3(2 * DI / 128, ROWS / 128), 512>>>(xh, xl, wih, wil, xr, 2 * DI, DM);

    // 2) depthwise causal conv (+b_in) + silu -> u
    conv_silu<<<(ROWS * DI) / 256, 256>>>(xr, b_in, conv_w, conv_b, u);

    // 3) x_proj: xp[2048,96] = u @ W_x^T
    gemm_skinny<<<ROWS / 16, 256>>>(u, W_x, xp);

    // 4) dt_proj + softplus (fp32): delta = softplus(xp[:, :64] @ W_dt^T + b_dt)
    gemm128<1><<<dim3(DI / 128, ROWS / 128), 256>>>(xp, XPW, W_dt, DTR, b_dt, delta, DI, DTR);

    // 5) chunked selective scan + gating (res gets +b_in fold) -> g
    scan_kernel<<<dim3(BSZ * NC, DI / 128), 128>>>(A_log, delta, u, xr, b_in, xp, g);

    // 6) out_proj (tensor core, bf16x3): out = g @ W_out^T, then +b_out
    split_bf16<<<(ROWS * DI + 255) / 256, 256>>>(g, gh, gl, ROWS * DI);
    split_bf16<<<(DM * DI + 255) / 256, 256>>>(W_out, woh, wol, DM * DI);
    gemm_bf16x3<<<dim3(DM / 128, ROWS / 128), 512>>>(gh, gl, woh, wol, out, DM, DI);
    add_bias<<<(ROWS * DM + 255) / 256, 256>>>(out, b_out, ROWS * DM);
}

// round 6
// speedup vs baseline: 1.7719x; 1.2537x over previous
#include <cuda_runtime.h>
#include <cuda_bf16.h>
#include <mma.h>
#include <math.h>
#include <stdint.h>

using namespace nvcuda;

// Problem constants (fixed shapes from reference setup_inputs)
#define BSZ   2
#define SEQ   1024
#define DM    1024
#define DI    2048
#define NS    16
#define DTR   64
#define ROWS  (BSZ*SEQ)     // 2048
#define CHUNK_T 256
#define NC    (SEQ/CHUNK_T) // 4
#define XPW   96            // dt_rank + 2*n_state

// ---------------- scratch (device globals; no allocation allowed) ----------
__device__ float g_xr[ROWS * 2 * DI];   // in_proj output (raw, bias folded later)
__device__ float g_u[ROWS * DI];        // conv+silu output
__device__ float g_xp[ROWS * XPW];      // x_proj output (dlt | B | C)
__device__ float g_xpp[4 * ROWS * XPW]; // x_proj split-K partials
__device__ float g_delta[ROWS * DI];    // softplus(dt_proj)

// bf16 hi/lo split buffers
__device__ __nv_bfloat16 g_xh[ROWS * DM],  g_xl[ROWS * DM];      // x split
__device__ __nv_bfloat16 g_wih[2*DI * DM], g_wil[2*DI * DM];     // W_in split
__device__ __nv_bfloat16 g_gh[ROWS * DI],  g_gl[ROWS * DI];      // gated scan out
__device__ __nv_bfloat16 g_woh[DM * DI],   g_wol[DM * DI];       // W_out split

// ---------------- cp.async helpers ------------------------------------------
__device__ __forceinline__ uint32_t smem_u32(const void* p) {
    uint32_t a;
    asm("{ .reg .u64 t; cvta.to.shared.u64 t, %1; cvt.u32.u64 %0, t; }"
        : "=r"(a) : "l"(p));
    return a;
}
__device__ __forceinline__ void cp8(uint32_t dst, const void* src) {
    asm volatile("cp.async.ca.shared.global [%0], [%1], 8;" :: "r"(dst), "l"(src));
}
#define CP_COMMIT() asm volatile("cp.async.commit_group;" ::: "memory")
#define CP_WAIT(n)  asm volatile("cp.async.wait_group %0;" :: "n"(n) : "memory")

// ---------------- bf16 hi/lo split ------------------------------------------
__global__ __launch_bounds__(256)
void split_bf16(const float* __restrict__ src,
                __nv_bfloat16* __restrict__ hi,
                __nv_bfloat16* __restrict__ lo, int n)
{
    int i = blockIdx.x * blockDim.x + threadIdx.x;
    if (i < n) {
        float v = src[i];
        __nv_bfloat16 h = __float2bfloat16(v);
        hi[i] = h;
        lo[i] = __float2bfloat16(v - __bfloat162float(h));
    }
}

// ============ bf16x3 wmma GEMM, cp.async double-buffered =====================
// C[M,N] = A[M,K] @ W[N,K]^T  (no bias; fused downstream).
// Block 128x128, BK=32, 256 threads = 8 warps (4 M x 2 N), warp tile 32x64.
// Smem: per stage 4 tiles (Ah,Al,Bh,Bl) of 128 x 40(bf16-padded) = 10240B each.
#define BKP      40
#define TILE_SB  (128 * BKP * 2)        // 10240 B
#define STAGE_SB (4 * TILE_SB)          // 40960 B
#define GEMM_DSM (2 * STAGE_SB)         // 81920 B

extern __shared__ char dsm[];

__global__ void __launch_bounds__(256)
gemm_wmma3(const __nv_bfloat16* __restrict__ Ah, const __nv_bfloat16* __restrict__ Al,
           const __nv_bfloat16* __restrict__ Bh, const __nv_bfloat16* __restrict__ Bl,
           float* __restrict__ C, int N, int K)
{
    const int tid = threadIdx.x;
    const int wid = tid >> 5;
    const int wr  = wid & 3;          // warp M row 0..3  (32 rows each)
    const int wc  = wid >> 2;         // warp N col 0..1  (64 cols each)
    const int m0  = blockIdx.y * 128;
    const int n0  = blockIdx.x * 128;

    const uint32_t sb0 = smem_u32(dsm);

    wmma::fragment<wmma::accumulator, 16, 16, 16, float> acc[2][4];
    #pragma unroll
    for (int i = 0; i < 2; i++)
        #pragma unroll
        for (int j = 0; j < 4; j++) wmma::fill_fragment(acc[i][j], 0.0f);

    // stage fill: 4 tiles x 128 rows x 8 chunks of 8B; 256 thr -> 4 chunks/tile
    auto fill = [&](int buf, int k0) {
        uint32_t sb = sb0 + buf * STAGE_SB;
        #pragma unroll
        for (int t = 0; t < 4; t++) {
            const __nv_bfloat16* src = (t == 0) ? Ah : (t == 1) ? Al : (t == 2) ? Bh : Bl;
            int rbase = (t < 2) ? m0 : n0;
            #pragma unroll
            for (int j = 0; j < 4; j++) {
                int id = tid + j * 256;
                int r = id >> 3, c = id & 7;
                cp8(sb + t * TILE_SB + r * (BKP * 2) + c * 8,
                    src + (size_t)(rbase + r) * K + k0 + c * 4);
            }
        }
    };

    const int S = K >> 5;
    fill(0, 0);
    CP_COMMIT();

    for (int s = 0; s < S; s++) {
        const int cur = s & 1;
        if (s + 1 < S) { fill(cur ^ 1, (s + 1) << 5); CP_COMMIT(); CP_WAIT(1); }
        else           { CP_WAIT(0); }
        __syncthreads();

        const __nv_bfloat16* Sa_h = (const __nv_bfloat16*)(dsm + cur * STAGE_SB);
        const __nv_bfloat16* Sa_l = Sa_h + 128 * BKP;
        const __nv_bfloat16* Sb_h = Sa_h + 2 * 128 * BKP;
        const __nv_bfloat16* Sb_l = Sa_h + 3 * 128 * BKP;

        #pragma unroll
        for (int kk = 0; kk < 32; kk += 16) {
            wmma::fragment<wmma::matrix_a, 16, 16, 16, __nv_bfloat16, wmma::row_major> ah[2], al[2];
            wmma::fragment<wmma::matrix_b, 16, 16, 16, __nv_bfloat16, wmma::col_major> bh[4], bl[4];
            #pragma unroll
            for (int i = 0; i < 2; i++) {
                int r = (wr * 32 + i * 16) * BKP + kk;
                wmma::load_matrix_sync(ah[i], Sa_h + r, BKP);
                wmma::load_matrix_sync(al[i], Sa_l + r, BKP);
            }
            #pragma unroll
            for (int j = 0; j < 4; j++) {
                int r = (wc * 64 + j * 16) * BKP + kk;
                wmma::load_matrix_sync(bh[j], Sb_h + r, BKP);
                wmma::load_matrix_sync(bl[j], Sb_l + r, BKP);
            }
            #pragma unroll
            for (int i = 0; i < 2; i++)
                #pragma unroll
                for (int j = 0; j < 4; j++) {
                    wmma::mma_sync(acc[i][j], ah[i], bh[j], acc[i][j]);
                    wmma::mma_sync(acc[i][j], ah[i], bl[j], acc[i][j]);
                    wmma::mma_sync(acc[i][j], al[i], bh[j], acc[i][j]);
                }
        }
        __syncthreads();
    }

    #pragma unroll
    for (int i = 0; i < 2; i++)
        #pragma unroll
        for (int j = 0; j < 4; j++) {
            float* p = C + (size_t)(m0 + wr * 32 + i * 16) * N + n0 + wc * 64 + j * 16;
            wmma::store_matrix_sync(p, acc[i][j], N, wmma::mem_row_major);
        }
}

// ---------------- dt_proj: delta = softplus(xp[:, :64] @ W_dt^T + b_dt) ------
// 64x64 tile, K=64 single pass, 256 threads, 4x4 per thread. 1024 CTAs.
__global__ __launch_bounds__(256)
void gemm_dt(const float* __restrict__ A,   // xp, lda=XPW
             const float* __restrict__ W,   // W_dt [DI, 64]
             const float* __restrict__ bias,
             float* __restrict__ C)         // delta [ROWS, DI]
{
    __shared__ float As[64][65];
    __shared__ float Ws[64][65];

    const int tid = threadIdx.x;
    const int m0 = blockIdx.y * 64;
    const int n0 = blockIdx.x * 64;

    #pragma unroll
    for (int j = 0; j < 4; j++) {
        int id = tid + j * 256;
        int r = id >> 4, c4 = (id & 15) << 2;
        float4 va = *(const float4*)(A + (size_t)(m0 + r) * XPW + c4);
        As[c4 + 0][r] = va.x; As[c4 + 1][r] = va.y;
        As[c4 + 2][r] = va.z; As[c4 + 3][r] = va.w;
        float4 vw = *(const float4*)(W + (size_t)(n0 + r) * DTR + c4);
        Ws[c4 + 0][r] = vw.x; Ws[c4 + 1][r] = vw.y;
        Ws[c4 + 2][r] = vw.z; Ws[c4 + 3][r] = vw.w;
    }
    __syncthreads();

    const int tx = tid & 15;
    const int ty = tid >> 4;
    float acc[4][4];
    #pragma unroll
    for (int i = 0; i < 4; i++)
        #pragma unroll
        for (int j = 0; j < 4; j++) acc[i][j] = 0.f;

    #pragma unroll 8
    for (int k = 0; k < 64; k++) {
        float a[4], b[4];
        #pragma unroll
        for (int i = 0; i < 4; i++) a[i] = As[k][ty * 4 + i];
        #pragma unroll
        for (int j = 0; j < 4; j++) b[j] = Ws[k][tx * 4 + j];
        #pragma unroll
        for (int i = 0; i < 4; i++)
            #pragma unroll
            for (int j = 0; j < 4; j++)
                acc[i][j] = fmaf(a[i], b[j], acc[i][j]);
    }

    #pragma unroll
    for (int i = 0; i < 4; i++) {
        int m = m0 + ty * 4 + i;
        #pragma unroll
        for (int j = 0; j < 4; j++) {
            int n = n0 + tx * 4 + j;
            float v = acc[i][j] + bias[n];
            v = fmaxf(v, 0.f) + log1pf(expf(-fabsf(v)));   // stable softplus
            C[(size_t)m * DI + n] = v;
        }
    }
}

// ---------------- skinny GEMM split-K: partials[ks] = u @ W_x^T (K slice) ----
__global__ __launch_bounds__(256)
void gemm_skinny(const float* __restrict__ A,
                 const float* __restrict__ W,
                 float* __restrict__ P)     // partials base
{
    __shared__ float As[32][17];
    __shared__ float Ws[32][97];

    const int tid = threadIdx.x;
    const int tx = tid & 31;
    const int ty = tid >> 5;
    const int m0 = blockIdx.x * 16;
    const int kb = blockIdx.y * (DI / 4);
    float* C = P + (size_t)blockIdx.y * ROWS * XPW;

    float acc[2][3];
    #pragma unroll
    for (int i = 0; i < 2; i++)
        #pragma unroll
        for (int j = 0; j < 3; j++) acc[i][j] = 0.f;

    for (int k0 = kb; k0 < kb + DI / 4; k0 += 32) {
        if (tid < 128) {
            int row = tid >> 3;
            int kq  = (tid & 7) << 2;
            float4 v = *(const float4*)(A + (size_t)(m0 + row) * DI + k0 + kq);
            As[kq + 0][row] = v.x; As[kq + 1][row] = v.y;
            As[kq + 2][row] = v.z; As[kq + 3][row] = v.w;
        }
        #pragma unroll
        for (int i = 0; i < 3; i++) {
            int f   = tid + i * 256;
            int row = f >> 3;
            int kq  = (f & 7) << 2;
            float4 v = *(const float4*)(W + (size_t)row * DI + k0 + kq);
            Ws[kq + 0][row] = v.x; Ws[kq + 1][row] = v.y;
            Ws[kq + 2][row] = v.z; Ws[kq + 3][row] = v.w;
        }
        __syncthreads();

        #pragma unroll
        for (int k = 0; k < 32; k++) {
            float a0 = As[k][ty * 2 + 0], a1 = As[k][ty * 2 + 1];
            float b0 = Ws[k][tx * 3 + 0], b1 = Ws[k][tx * 3 + 1], b2 = Ws[k][tx * 3 + 2];
            acc[0][0] = fmaf(a0, b0, acc[0][0]); acc[0][1] = fmaf(a0, b1, acc[0][1]); acc[0][2] = fmaf(a0, b2, acc[0][2]);
            acc[1][0] = fmaf(a1, b0, acc[1][0]); acc[1][1] = fmaf(a1, b1, acc[1][1]); acc[1][2] = fmaf(a1, b2, acc[1][2]);
        }
        __syncthreads();
    }

    #pragma unroll
    for (int i = 0; i < 2; i++)
        #pragma unroll
        for (int j = 0; j < 3; j++)
            C[(size_t)(m0 + ty * 2 + i) * XPW + tx * 3 + j] = acc[i][j];
}

__global__ __launch_bounds__(256)
void reduce_xp(const float* __restrict__ P, float* __restrict__ xp)
{
    int i = blockIdx.x * blockDim.x + threadIdx.x;
    if (i < ROWS * XPW)
        xp[i] = P[i] + P[i + ROWS * XPW] + P[i + 2 * ROWS * XPW] + P[i + 3 * ROWS * XPW];
}

// ---------------- causal depthwise conv (k=3) + SiLU, float4 -----------------
__global__ __launch_bounds__(256)
void conv_silu(const float* __restrict__ xr,
               const float* __restrict__ b_in,
               const float* __restrict__ cw,
               const float* __restrict__ cb,
               float* __restrict__ u)
{
    int q   = blockIdx.x * blockDim.x + threadIdx.x;   // 0 .. ROWS*DI/4-1
    int d4  = (q << 2) & (DI - 1);
    int row = q >> 9;                                   // (q*4) >> 11
    int l   = row & (SEQ - 1);
    const float* base = xr + (size_t)row * (2 * DI) + d4;
    float4 bin = *(const float4*)(b_in + d4);
    float4 cb4 = *(const float4*)(cb + d4);
    float4 c0 = *(const float4*)(base);
    float4 c1 = (l >= 1) ? *(const float4*)(base - 2 * DI) : make_float4(0, 0, 0, 0);
    float4 c2 = (l >= 2) ? *(const float4*)(base - 4 * DI) : make_float4(0, 0, 0, 0);
    float m1 = (l >= 1) ? 1.f : 0.f;
    float m2 = (l >= 2) ? 1.f : 0.f;

    float4 o;
    #pragma unroll
    for (int t = 0; t < 4; t++) {
        float w0 = cw[(d4 + t) * 3 + 0], w1 = cw[(d4 + t) * 3 + 1], w2 = cw[(d4 + t) * 3 + 2];
        float b  = ((const float*)&bin)[t];
        float x0 = ((const float*)&c0)[t] + b;
        float x1 = ((const float*)&c1)[t] + b;
        float x2 = ((const float*)&c2)[t] + b;
        float a = fmaf(w2, x0, ((const float*)&cb4)[t]);
        a = fmaf(w1 * m1, x1, a);
        a = fmaf(w0 * m2, x2, a);
        ((float*)&o)[t] = a / (1.f + __expf(-a));
    }
    *(float4*)(u + ((size_t)row * DI + d4)) = o;
}

// ---------------- chunked selective scan + gating, emits bf16 hi/lo ----------
__global__ __launch_bounds__(128)
void scan_kernel(const float* __restrict__ A_log,
                 const float* __restrict__ delta,
                 const float* __restrict__ u,
                 const float* __restrict__ xr,
                 const float* __restrict__ b_in,
                 const float* __restrict__ xp,
                 __nv_bfloat16* __restrict__ gh,
                 __nv_bfloat16* __restrict__ gl)
{
    const int bc = blockIdx.x;
    const int b  = bc / NC;
    const int c  = bc - b * NC;
    const int d  = blockIdx.y * 128 + threadIdx.x;
    const int row0 = b * SEQ + c * CHUNK_T;
    const float bres = b_in[DI + d];

    float Aa[NS], st[NS];
    #pragma unroll
    for (int n = 0; n < NS; n++) {
        Aa[n] = -expf(A_log[d * NS + n]);
        st[n] = 0.f;
    }

    __shared__ float Bs[16][NS];
    __shared__ float Cs[16][NS];

    for (int t0 = 0; t0 < CHUNK_T; t0 += 16) {
        __syncthreads();
        #pragma unroll
        for (int i = 0; i < 4; i++) {
            int e   = threadIdx.x + i * 128;
            int tl  = e >> 5;
            int rem = e & 31;
            float v = xp[(size_t)(row0 + t0 + tl) * XPW + DTR + rem];
            if (rem < NS) Bs[tl][rem]       = v;
            else          Cs[tl][rem - NS]  = v;
        }
        __syncthreads();

        #pragma unroll 4
        for (int tt = 0; tt < 16; tt++) {
            const int row = row0 + t0 + tt;
            float dv = delta[(size_t)row * DI + d];
            float uv = u[(size_t)row * DI + d];
            float rv = xr[(size_t)row * (2 * DI) + DI + d] + bres;
            float du = dv * uv;
            float y  = 0.f;
            #pragma unroll
            for (int n = 0; n < NS; n++) {
                float a = __expf(dv * Aa[n]);
                st[n] = fmaf(a, st[n], du * Bs[tt][n]);
                y     = fmaf(st[n], Cs[tt][n], y);
            }
            float gate = rv / (1.f + __expf(-rv));
            float v = y * gate;
            __nv_bfloat16 h = __float2bfloat16(v);
            size_t idx = (size_t)row * DI + d;
            gh[idx] = h;
            gl[idx] = __float2bfloat16(v - __bfloat162float(h));
        }
    }
}

// ---------------- final bias add --------------------------------------------
__global__ __launch_bounds__(256)
void add_bias(float* __restrict__ C, const float* __restrict__ b, int n)
{
    int i = blockIdx.x * blockDim.x + threadIdx.x;
    if (i < n) C[i] += b[i & (DM - 1)];
}

// ---------------- launch ----------------------------------------------------
extern "C" void kernel_launch(void* const* d_in, const int* in_sizes, int n_in,
                              void* d_out, int out_size)
{
    const float* x      = (const float*)d_in[0];
    const float* W_in   = (const float*)d_in[1];
    const float* b_in   = (const float*)d_in[2];
    const float* conv_w = (const float*)d_in[3];
    const float* conv_b = (const float*)d_in[4];
    const float* W_x    = (const float*)d_in[5];
    const float* W_dt   = (const float*)d_in[6];
    const float* b_dt   = (const float*)d_in[7];
    const float* A_log  = (const float*)d_in[8];
    const float* W_out  = (const float*)d_in[9];
    const float* b_out  = (const float*)d_in[10];
    float* out = (float*)d_out;

    float *xr, *u, *xp, *xpp, *delta;
    cudaGetSymbolAddress((void**)&xr,    g_xr);
    cudaGetSymbolAddress((void**)&u,     g_u);
    cudaGetSymbolAddress((void**)&xp,    g_xp);
    cudaGetSymbolAddress((void**)&xpp,   g_xpp);
    cudaGetSymbolAddress((void**)&delta, g_delta);

    __nv_bfloat16 *xh, *xl, *wih, *wil, *gh, *gl, *woh, *wol;
    cudaGetSymbolAddress((void**)&xh,  g_xh);
    cudaGetSymbolAddress((void**)&xl,  g_xl);
    cudaGetSymbolAddress((void**)&wih, g_wih);
    cudaGetSymbolAddress((void**)&wil, g_wil);
    cudaGetSymbolAddress((void**)&gh,  g_gh);
    cudaGetSymbolAddress((void**)&gl,  g_gl);
    cudaGetSymbolAddress((void**)&woh, g_woh);
    cudaGetSymbolAddress((void**)&wol, g_wol);

    static bool attr_done = false;
    if (!attr_done) {
        cudaFuncSetAttribute(gemm_wmma3, cudaFuncAttributeMaxDynamicSharedMemorySize, GEMM_DSM);
        attr_done = true;
    }

    // 0) bf16 hi/lo splits for in_proj operands
    split_bf16<<<(ROWS * DM + 255) / 256, 256>>>(x, xh, xl, ROWS * DM);
    split_bf16<<<(2 * DI * DM + 255) / 256, 256>>>(W_in, wih, wil, 2 * DI * DM);

    // 1) in_proj: xr_raw[2048,4096] = x @ W_in^T  (bias folded downstream)
    gemm_wmma3<<<dim3(2 * DI / 128, ROWS / 128), 256, GEMM_DSM>>>(
        xh, xl, wih, wil, xr, 2 * DI, DM);

    // 2) depthwise causal conv (+b_in) + silu -> u
    conv_silu<<<(ROWS * DI / 4) / 256, 256>>>(xr, b_in, conv_w, conv_b, u);

    // 3) x_proj split-K: xp[2048,96] = u @ W_x^T
    gemm_skinny<<<dim3(ROWS / 16, 4), 256>>>(u, W_x, xpp);
    reduce_xp<<<(ROWS * XPW + 255) / 256, 256>>>(xpp, xp);

    // 4) dt_proj + softplus: delta = softplus(xp[:, :64] @ W_dt^T + b_dt)
    gemm_dt<<<dim3(DI / 64, ROWS / 64), 256>>>(xp, W_dt, b_dt, delta);

    // 5) chunked selective scan + gating -> bf16 hi/lo of y*silu(res)
    scan_kernel<<<dim3(BSZ * NC, DI / 128), 128>>>(A_log, delta, u, xr, b_in, xp, gh, gl);

    // 6) out_proj: out = g @ W_out^T, then + b_out
    split_bf16<<<(DM * DI + 255) / 256, 256>>>(W_out, woh, wol, DM * DI);
    gemm_wmma3<<<dim3(DM / 128, ROWS / 128), 256, GEMM_DSM>>>(
        gh, gl, woh, wol, out, DM, DI);
    add_bias<<<(ROWS * DM + 255) / 256, 256>>>(out, b_out, ROWS * DM);
}